// round 1
// baseline (speedup 1.0000x reference)
#include <cuda_runtime.h>
#include <cuda_bf16.h>
#include <math_constants.h>

#define D_MODEL 1024
#define NUM_HEADS 16
#define HEAD_DIM 64
#define BATCH 2
#define SEQ 2048
#define PHI_F 8
#define MTOT (BATCH * SEQ)   // 4096

// ---------------- scratch (device globals, no runtime allocation) ------------
__device__ float g_q[MTOT * D_MODEL];
__device__ float g_k[MTOT * D_MODEL];
__device__ float g_v[MTOT * D_MODEL];
__device__ float g_attn[MTOT * D_MODEL];
__device__ float g_scale[MTOT];

// ---------------- per-row softmax scale --------------------------------------
// softmax((s - c)/d) == softmax(s/d) for per-row constants c and positive d.
// d = max(mean(phi), 1e-6); raw score already has 1/sqrt(64)=1/8.
__global__ void scale_kernel(const float* __restrict__ phi, float* __restrict__ scale) {
    int i = blockIdx.x * blockDim.x + threadIdx.x;
    if (i < MTOT) {
        float s = 0.f;
#pragma unroll
        for (int j = 0; j < PHI_F; ++j) s += phi[i * PHI_F + j];
        float ph = s * (1.0f / PHI_F);
        scale[i] = 1.0f / (8.0f * fmaxf(ph, 1e-6f));
    }
}

// ---------------- SGEMM: C[M,N] = A[M,K] @ W[N,K]^T + bias[N] ----------------
// 128x128 block tile, BK=16, 256 threads, 8x8 micro-tile per thread.
__global__ __launch_bounds__(256, 2)
void sgemm_nt(const float* __restrict__ A, const float* __restrict__ W,
              const float* __restrict__ bias, float* __restrict__ C,
              int M, int N, int K) {
    __shared__ float As[16][128];
    __shared__ float Bs[16][128];

    const int tid = threadIdx.x;
    const int bm = blockIdx.y * 128;
    const int bn = blockIdx.x * 128;
    const int tx = tid & 15;         // 0..15  -> N
    const int ty = tid >> 4;         // 0..15  -> M
    const int lr = tid >> 2;         // 0..63 : load row
    const int lk = (tid & 3) * 4;    // 0,4,8,12 : load k offset

    float acc[8][8];
#pragma unroll
    for (int i = 0; i < 8; ++i)
#pragma unroll
        for (int j = 0; j < 8; ++j) acc[i][j] = 0.f;

    for (int k0 = 0; k0 < K; k0 += 16) {
#pragma unroll
        for (int half = 0; half < 2; ++half) {
            int row = lr + half * 64;
            float4 av = *(const float4*)&A[(size_t)(bm + row) * K + k0 + lk];
            As[lk + 0][row] = av.x; As[lk + 1][row] = av.y;
            As[lk + 2][row] = av.z; As[lk + 3][row] = av.w;
            float4 bv = *(const float4*)&W[(size_t)(bn + row) * K + k0 + lk];
            Bs[lk + 0][row] = bv.x; Bs[lk + 1][row] = bv.y;
            Bs[lk + 2][row] = bv.z; Bs[lk + 3][row] = bv.w;
        }
        __syncthreads();
#pragma unroll
        for (int kk = 0; kk < 16; ++kk) {
            float ra[8], rb[8];
            *(float4*)&ra[0] = *(const float4*)&As[kk][ty * 8];
            *(float4*)&ra[4] = *(const float4*)&As[kk][ty * 8 + 4];
            *(float4*)&rb[0] = *(const float4*)&Bs[kk][tx * 8];
            *(float4*)&rb[4] = *(const float4*)&Bs[kk][tx * 8 + 4];
#pragma unroll
            for (int i = 0; i < 8; ++i)
#pragma unroll
                for (int j = 0; j < 8; ++j) acc[i][j] += ra[i] * rb[j];
        }
        __syncthreads();
    }

#pragma unroll
    for (int i = 0; i < 8; ++i) {
        int row = bm + ty * 8 + i;
#pragma unroll
        for (int j4 = 0; j4 < 8; j4 += 4) {
            int col = bn + tx * 8 + j4;
            float4 o;
            o.x = acc[i][j4 + 0] + bias[col + 0];
            o.y = acc[i][j4 + 1] + bias[col + 1];
            o.z = acc[i][j4 + 2] + bias[col + 2];
            o.w = acc[i][j4 + 3] + bias[col + 3];
            *(float4*)&C[(size_t)row * N + col] = o;
        }
    }
}

// ---------------- flash attention (fp32, per-row score scale) ----------------
// Block: one (b, h, 64-query tile). 256 threads = 16x16; each thread owns a
// 4x4 micro-tile (rows ty*4.., cols tx*4..).
#define BQ 64
#define BKV 64
#define SP 68   // padded smem row stride (68*4 bytes = 16B-aligned rows)

__global__ __launch_bounds__(256)
void flash_kernel(const float* __restrict__ Q, const float* __restrict__ K,
                  const float* __restrict__ V, const float* __restrict__ rscale,
                  float* __restrict__ O) {
    extern __shared__ float sm[];
    float* Qt = sm;                         // [HEAD_DIM][SP], Qt[d][r]
    float* Kt = Qt + HEAD_DIM * SP;         // [HEAD_DIM][SP], Kt[d][c]; reused as Pt[k][r]
    float* Vs = Kt + HEAD_DIM * SP;         // [BKV][SP],      Vs[k][d]
    float* row_m = Vs + BKV * SP;           // [BQ]
    float* row_l = row_m + BQ;              // [BQ]
    float* row_c = row_l + BQ;              // [BQ]
    float* qsc   = row_c + BQ;              // [BQ]
    float* Pt = Kt;                         // alias

    const int tid = threadIdx.x;
    const int b = blockIdx.z, h = blockIdx.y;
    const int q0 = blockIdx.x * BQ;
    const int tx = tid & 15, ty = tid >> 4;
    const int r0 = ty * 4, c0 = tx * 4;

    // load Q tile (transposed to d-major)
#pragma unroll
    for (int it = 0; it < BQ * HEAD_DIM / 4 / 256; ++it) {
        int i = tid + it * 256;
        int r = i / (HEAD_DIM / 4);
        int d4 = (i % (HEAD_DIM / 4)) * 4;
        float4 v = *(const float4*)&Q[(size_t)(b * SEQ + q0 + r) * D_MODEL + h * HEAD_DIM + d4];
        Qt[(d4 + 0) * SP + r] = v.x; Qt[(d4 + 1) * SP + r] = v.y;
        Qt[(d4 + 2) * SP + r] = v.z; Qt[(d4 + 3) * SP + r] = v.w;
    }
    if (tid < BQ) {
        qsc[tid] = rscale[b * SEQ + q0 + tid];
        row_m[tid] = -CUDART_INF_F;
        row_l[tid] = 0.f;
    }
    __syncthreads();

    float qs[4];
#pragma unroll
    for (int i = 0; i < 4; ++i) qs[i] = qsc[r0 + i];

    float acc[4][4];
#pragma unroll
    for (int i = 0; i < 4; ++i)
#pragma unroll
        for (int j = 0; j < 4; ++j) acc[i][j] = 0.f;

    for (int kt = 0; kt < SEQ / BKV; ++kt) {
        const int k0 = kt * BKV;
        // load K (transposed) and V (row-major)
#pragma unroll
        for (int it = 0; it < BKV * HEAD_DIM / 4 / 256; ++it) {
            int i = tid + it * 256;
            int r = i / (HEAD_DIM / 4);
            int d4 = (i % (HEAD_DIM / 4)) * 4;
            size_t gro = (size_t)(b * SEQ + k0 + r) * D_MODEL + h * HEAD_DIM + d4;
            float4 kv = *(const float4*)&K[gro];
            Kt[(d4 + 0) * SP + r] = kv.x; Kt[(d4 + 1) * SP + r] = kv.y;
            Kt[(d4 + 2) * SP + r] = kv.z; Kt[(d4 + 3) * SP + r] = kv.w;
            *(float4*)&Vs[r * SP + d4] = *(const float4*)&V[gro];
        }
        __syncthreads();

        // ---- phase A: scores micro-tile + tile row max ----
        float s[4][4];
#pragma unroll
        for (int i = 0; i < 4; ++i)
#pragma unroll
            for (int j = 0; j < 4; ++j) s[i][j] = 0.f;
#pragma unroll
        for (int d = 0; d < HEAD_DIM; ++d) {
            float qv[4], kv[4];
            *(float4*)qv = *(const float4*)&Qt[d * SP + r0];
            *(float4*)kv = *(const float4*)&Kt[d * SP + c0];
#pragma unroll
            for (int i = 0; i < 4; ++i)
#pragma unroll
                for (int j = 0; j < 4; ++j) s[i][j] += qv[i] * kv[j];
        }
        float rm[4];
#pragma unroll
        for (int i = 0; i < 4; ++i) {
#pragma unroll
            for (int j = 0; j < 4; ++j) s[i][j] *= qs[i];
            rm[i] = fmaxf(fmaxf(s[i][0], s[i][1]), fmaxf(s[i][2], s[i][3]));
#pragma unroll
            for (int o = 8; o >= 1; o >>= 1)
                rm[i] = fmaxf(rm[i], __shfl_xor_sync(0xffffffffu, rm[i], o));
        }
        if (tx == 0) {
#pragma unroll
            for (int i = 0; i < 4; ++i) {
                float mo = row_m[r0 + i];
                float mn = fmaxf(mo, rm[i]);
                row_m[r0 + i] = mn;
                row_c[r0 + i] = __expf(mo - mn);
            }
        }
        __syncthreads();

        // ---- phase B: exponentiate, write P^T (into Kt buffer), row sums ----
        float ps[4];
#pragma unroll
        for (int i = 0; i < 4; ++i) {
            float mn = row_m[r0 + i];
            ps[i] = 0.f;
#pragma unroll
            for (int j = 0; j < 4; ++j) {
                s[i][j] = __expf(s[i][j] - mn);
                ps[i] += s[i][j];
            }
#pragma unroll
            for (int o = 8; o >= 1; o >>= 1)
                ps[i] += __shfl_xor_sync(0xffffffffu, ps[i], o);
        }
#pragma unroll
        for (int j = 0; j < 4; ++j) {
            float4 pv = make_float4(s[0][j], s[1][j], s[2][j], s[3][j]);
            *(float4*)&Pt[(c0 + j) * SP + r0] = pv;
        }
        float cr[4];
#pragma unroll
        for (int i = 0; i < 4; ++i) cr[i] = row_c[r0 + i];
        if (tx == 0) {
#pragma unroll
            for (int i = 0; i < 4; ++i)
                row_l[r0 + i] = row_l[r0 + i] * cr[i] + ps[i];
        }
#pragma unroll
        for (int i = 0; i < 4; ++i)
#pragma unroll
            for (int j = 0; j < 4; ++j) acc[i][j] *= cr[i];
        __syncthreads();

        // ---- phase C: O += P @ V ----
#pragma unroll
        for (int k = 0; k < BKV; ++k) {
            float pv[4], vv[4];
            *(float4*)pv = *(const float4*)&Pt[k * SP + r0];
            *(float4*)vv = *(const float4*)&Vs[k * SP + c0];
#pragma unroll
            for (int i = 0; i < 4; ++i)
#pragma unroll
                for (int j = 0; j < 4; ++j) acc[i][j] += pv[i] * vv[j];
        }
        __syncthreads();
    }

    // epilogue
#pragma unroll
    for (int i = 0; i < 4; ++i) {
        float inv = 1.0f / row_l[r0 + i];
        float4 o = make_float4(acc[i][0] * inv, acc[i][1] * inv,
                               acc[i][2] * inv, acc[i][3] * inv);
        *(float4*)&O[(size_t)(b * SEQ + q0 + r0 + i) * D_MODEL + h * HEAD_DIM + c0] = o;
    }
}

// ---------------- launch ------------------------------------------------------
extern "C" void kernel_launch(void* const* d_in, const int* in_sizes, int n_in,
                              void* d_out, int out_size) {
    const float* query = (const float*)d_in[0];
    const float* key   = (const float*)d_in[1];
    const float* value = (const float*)d_in[2];
    const float* phi   = (const float*)d_in[3];
    // d_in[4] = logvar (cancels in softmax), d_in[13]/[14] = w_sigma/w_phi (cancel)
    const float* Wq = (const float*)d_in[5];
    const float* bq = (const float*)d_in[6];
    const float* Wk = (const float*)d_in[7];
    const float* bk = (const float*)d_in[8];
    const float* Wv = (const float*)d_in[9];
    const float* bv = (const float*)d_in[10];
    const float* Wo = (const float*)d_in[11];
    const float* bo = (const float*)d_in[12];
    float* out = (float*)d_out;

    float *q_p, *k_p, *v_p, *attn_p, *scale_p;
    cudaGetSymbolAddress((void**)&q_p, g_q);
    cudaGetSymbolAddress((void**)&k_p, g_k);
    cudaGetSymbolAddress((void**)&v_p, g_v);
    cudaGetSymbolAddress((void**)&attn_p, g_attn);
    cudaGetSymbolAddress((void**)&scale_p, g_scale);

    scale_kernel<<<(MTOT + 255) / 256, 256>>>(phi, scale_p);

    dim3 ggrid(D_MODEL / 128, MTOT / 128);
    sgemm_nt<<<ggrid, 256>>>(query, Wq, bq, q_p, MTOT, D_MODEL, D_MODEL);
    sgemm_nt<<<ggrid, 256>>>(key,   Wk, bk, k_p, MTOT, D_MODEL, D_MODEL);
    sgemm_nt<<<ggrid, 256>>>(value, Wv, bv, v_p, MTOT, D_MODEL, D_MODEL);

    const int smem = (3 * HEAD_DIM * SP + 4 * BQ) * sizeof(float);
    cudaFuncSetAttribute(flash_kernel, cudaFuncAttributeMaxDynamicSharedMemorySize, smem);
    dim3 fgrid(SEQ / BQ, NUM_HEADS, BATCH);
    flash_kernel<<<fgrid, 256, smem>>>(q_p, k_p, v_p, scale_p, attn_p);

    sgemm_nt<<<ggrid, 256>>>(attn_p, Wo, bo, out, MTOT, D_MODEL, D_MODEL);
}

// round 3
// speedup vs baseline: 6.1667x; 6.1667x over previous
#include <cuda_runtime.h>
#include <cuda_fp16.h>
#include <math_constants.h>
#include <cstdint>

#define D_MODEL 1024
#define NUM_HEADS 16
#define HEAD_DIM 64
#define BATCH 2
#define SEQ 2048
#define PHI_F 8
#define MTOT (BATCH * SEQ)   // 4096
#define LOG2E 1.4426950408889634f

// ---------------- scratch (device globals, no runtime allocation) ------------
__device__ __half g_hA[MTOT * D_MODEL];      // fp16 activations (reused)
__device__ __half g_hW[D_MODEL * D_MODEL];   // fp16 weights (reused)
__device__ __half g_hq[MTOT * D_MODEL];
__device__ __half g_hk[MTOT * D_MODEL];
__device__ __half g_hv[MTOT * D_MODEL];
__device__ __half g_hattn[MTOT * D_MODEL];
__device__ float  g_scale[MTOT];

// ======================= small helpers =======================================
__device__ __forceinline__ uint32_t cvta_shared_u32(const void* p) {
    uint32_t a;
    asm("{ .reg .u64 t; cvta.to.shared.u64 t, %1; cvt.u32.u64 %0, t; }"
        : "=r"(a) : "l"(p));
    return a;
}
__device__ __forceinline__ void cpa16(uint32_t s, const void* g) {
    asm volatile("cp.async.cg.shared.global [%0], [%1], 16;\n" :: "r"(s), "l"(g));
}
#define CP_COMMIT() asm volatile("cp.async.commit_group;\n" ::: "memory")
#define CP_WAIT(n)  asm volatile("cp.async.wait_group %0;\n" :: "n"(n) : "memory")

__device__ __forceinline__ void ldsm_x4(uint32_t* r, uint32_t addr) {
    asm volatile("ldmatrix.sync.aligned.m8n8.x4.shared.b16 {%0,%1,%2,%3}, [%4];"
                 : "=r"(r[0]), "=r"(r[1]), "=r"(r[2]), "=r"(r[3]) : "r"(addr));
}
__device__ __forceinline__ void ldsm_x4_t(uint32_t* r, uint32_t addr) {
    asm volatile("ldmatrix.sync.aligned.m8n8.x4.trans.shared.b16 {%0,%1,%2,%3}, [%4];"
                 : "=r"(r[0]), "=r"(r[1]), "=r"(r[2]), "=r"(r[3]) : "r"(addr));
}
__device__ __forceinline__ void mma16816(float* d, const uint32_t* a,
                                         uint32_t b0, uint32_t b1) {
    asm volatile(
        "mma.sync.aligned.m16n8k16.row.col.f32.f16.f16.f32 "
        "{%0,%1,%2,%3}, {%4,%5,%6,%7}, {%8,%9}, {%0,%1,%2,%3};"
        : "+f"(d[0]), "+f"(d[1]), "+f"(d[2]), "+f"(d[3])
        : "r"(a[0]), "r"(a[1]), "r"(a[2]), "r"(a[3]), "r"(b0), "r"(b1));
}
__device__ __forceinline__ uint32_t pack_h2(float x, float y) {
    __half2 h = __floats2half2_rn(x, y);
    return *reinterpret_cast<uint32_t*>(&h);
}

// ---------------- per-row softmax scale (log2e folded in) --------------------
__global__ void scale_kernel(const float* __restrict__ phi, float* __restrict__ scale) {
    int i = blockIdx.x * blockDim.x + threadIdx.x;
    if (i < MTOT) {
        float s = 0.f;
#pragma unroll
        for (int j = 0; j < PHI_F; ++j) s += phi[i * PHI_F + j];
        float ph = s * (1.0f / PHI_F);
        scale[i] = LOG2E / (8.0f * fmaxf(ph, 1e-6f));
    }
}

// ---------------- fp32 -> fp16 conversion ------------------------------------
__global__ void f2h_kernel(const float4* __restrict__ in, uint4* __restrict__ out, int n8) {
    int i = blockIdx.x * blockDim.x + threadIdx.x;
    if (i < n8) {
        float4 x = in[2 * i], y = in[2 * i + 1];
        uint4 o;
        o.x = pack_h2(x.x, x.y); o.y = pack_h2(x.z, x.w);
        o.z = pack_h2(y.x, y.y); o.w = pack_h2(y.z, y.w);
        out[i] = o;
    }
}

// ============== fp16 mma GEMM: C[M,N] = A[M,K] @ W[N,K]^T + bias =============
// 128x128 tile, BK=32, double-buffered cp.async, 8 warps (4x2), warp = 32x64.
#define GS 40                        // smem row stride in halfs (80B, conflict-free)
#define GSTG (128 * GS)              // halfs per matrix per stage

template <typename OutT>
__global__ __launch_bounds__(256, 2)
void gemm_h(const __half* __restrict__ A, const __half* __restrict__ W,
            const float* __restrict__ bias, OutT* __restrict__ C) {
    __shared__ __half sA[2 * GSTG];
    __shared__ __half sB[2 * GSTG];

    const int tid = threadIdx.x;
    const int wid = tid >> 5, lane = tid & 31;
    const int gid = lane >> 2, tig = lane & 3;
    const int bm = blockIdx.y * 128;
    const int bn = blockIdx.x * 128;
    const uint32_t sa0 = cvta_shared_u32(sA);
    const uint32_t sb0 = cvta_shared_u32(sB);

    // loader indices: 512 16B-chunks per matrix-stage; 4 chunks per row
    const int lrow = tid >> 2, lkc = (tid & 3) * 8;

    auto load_stage = [&](int kt, int st) {
        const int k0 = kt * 32;
        uint32_t da = sa0 + (uint32_t)(st * GSTG + lrow * GS + lkc) * 2;
        uint32_t db = sb0 + (uint32_t)(st * GSTG + lrow * GS + lkc) * 2;
#pragma unroll
        for (int i = 0; i < 2; ++i) {
            cpa16(da + (uint32_t)(i * 64 * GS) * 2, A + (size_t)(bm + lrow + i * 64) * D_MODEL + k0 + lkc);
            cpa16(db + (uint32_t)(i * 64 * GS) * 2, W + (size_t)(bn + lrow + i * 64) * D_MODEL + k0 + lkc);
        }
        CP_COMMIT();
    };

    float acc[2][8][4];
#pragma unroll
    for (int m = 0; m < 2; ++m)
#pragma unroll
        for (int n = 0; n < 8; ++n)
#pragma unroll
            for (int k = 0; k < 4; ++k) acc[m][n][k] = 0.f;

    const int sub = lane >> 3, r = lane & 7;
    // lane base offsets (halfs) for ldmatrix
    const int aRow = (wid & 3) * 32 + ((sub & 1) ? 8 : 0) + r;
    const int aCol = (sub & 2) ? 8 : 0;
    const int bRow = (wid >> 2) * 64 + ((sub & 2) ? 8 : 0) + r;
    const int bCol = (sub & 1) ? 8 : 0;

    load_stage(0, 0);

    const int NT = D_MODEL / 32;
    for (int kt = 0; kt < NT; ++kt) {
        const int st = kt & 1;
        if (kt + 1 < NT) { load_stage(kt + 1, st ^ 1); CP_WAIT(1); }
        else             { CP_WAIT(0); }
        __syncthreads();

        const uint32_t aBase = sa0 + (uint32_t)(st * GSTG + aRow * GS + aCol) * 2;
        const uint32_t bBase = sb0 + (uint32_t)(st * GSTG + bRow * GS + bCol) * 2;
#pragma unroll
        for (int ks = 0; ks < 2; ++ks) {
            uint32_t af[2][4];
            ldsm_x4(af[0], aBase + (uint32_t)(ks * 16) * 2);
            ldsm_x4(af[1], aBase + (uint32_t)(16 * GS + ks * 16) * 2);
#pragma unroll
            for (int np = 0; np < 4; ++np) {
                uint32_t bf[4];
                ldsm_x4(bf, bBase + (uint32_t)(np * 16 * GS + ks * 16) * 2);
#pragma unroll
                for (int m = 0; m < 2; ++m) {
                    mma16816(acc[m][2 * np + 0], af[m], bf[0], bf[1]);
                    mma16816(acc[m][2 * np + 1], af[m], bf[2], bf[3]);
                }
            }
        }
        __syncthreads();
    }

    // epilogue
#pragma unroll
    for (int m = 0; m < 2; ++m) {
        int row0 = bm + (wid & 3) * 32 + m * 16 + gid;
#pragma unroll
        for (int n = 0; n < 8; ++n) {
            int col = bn + (wid >> 2) * 64 + n * 8 + 2 * tig;
            float b0 = bias[col], b1 = bias[col + 1];
            if constexpr (sizeof(OutT) == 2) {
                __half2* p0 = (__half2*)((__half*)C + (size_t)row0 * D_MODEL + col);
                __half2* p1 = (__half2*)((__half*)C + (size_t)(row0 + 8) * D_MODEL + col);
                *p0 = __floats2half2_rn(acc[m][n][0] + b0, acc[m][n][1] + b1);
                *p1 = __floats2half2_rn(acc[m][n][2] + b0, acc[m][n][3] + b1);
            } else {
                float2* p0 = (float2*)((float*)C + (size_t)row0 * D_MODEL + col);
                float2* p1 = (float2*)((float*)C + (size_t)(row0 + 8) * D_MODEL + col);
                *p0 = make_float2(acc[m][n][0] + b0, acc[m][n][1] + b1);
                *p1 = make_float2(acc[m][n][2] + b0, acc[m][n][3] + b1);
            }
        }
    }
}

// ============== fp16 mma flash attention ====================================
// 256 threads = 8 warps; BQ=128 (16 rows/warp), BKV=64, double-buffered K/V.
#define FBQ 128
#define FBK 64
#define FS 72                         // smem stride (halfs), conflict-free
#define FNT (SEQ / FBK)               // 32 kv tiles

__global__ __launch_bounds__(256)
void flash_h(const __half* __restrict__ Q, const __half* __restrict__ K,
             const __half* __restrict__ V, const float* __restrict__ rscale,
             __half* __restrict__ O) {
    extern __shared__ __half fsm[];
    __half* Qs = fsm;                          // [128][FS]
    __half* Ks = Qs + FBQ * FS;                // [2][64][FS]
    __half* Vs = Ks + 2 * FBK * FS;            // [2][64][FS]

    const int tid = threadIdx.x;
    const int wid = tid >> 5, lane = tid & 31;
    const int gid = lane >> 2, tig = lane & 3;
    const int b = blockIdx.z, h = blockIdx.y;
    const int q0 = blockIdx.x * FBQ;

    const uint32_t qs0 = cvta_shared_u32(Qs);
    const uint32_t ks0 = cvta_shared_u32(Ks);
    const uint32_t vs0 = cvta_shared_u32(Vs);

    // ---- loaders ----
    auto load_q = [&]() {
#pragma unroll
        for (int i = 0; i < 4; ++i) {
            int idx = tid + i * 256;               // 1024 chunks
            int row = idx >> 3, kc = (idx & 7) * 8;
            cpa16(qs0 + (uint32_t)(row * FS + kc) * 2,
                  Q + (size_t)(b * SEQ + q0 + row) * D_MODEL + h * HEAD_DIM + kc);
        }
    };
    auto load_kv = [&](int kt, int st) {
        const int k0 = kt * FBK;
#pragma unroll
        for (int i = 0; i < 2; ++i) {
            int idx = tid + i * 256;               // 512 chunks
            int row = idx >> 3, kc = (idx & 7) * 8;
            size_t g = (size_t)(b * SEQ + k0 + row) * D_MODEL + h * HEAD_DIM + kc;
            cpa16(ks0 + (uint32_t)(st * FBK * FS + row * FS + kc) * 2, K + g);
            cpa16(vs0 + (uint32_t)(st * FBK * FS + row * FS + kc) * 2, V + g);
        }
        CP_COMMIT();
    };

    load_q(); load_kv(0, 0); CP_COMMIT();
    load_kv(1, 1);

    // per-thread softmax state (rows: a = wid*16+gid, b = +8)
    const int rowA = q0 + wid * 16 + gid;
    const float qsA = rscale[b * SEQ + rowA];
    const float qsB = rscale[b * SEQ + rowA + 8];
    float mA = -CUDART_INF_F, mB = -CUDART_INF_F, lA = 0.f, lB = 0.f;
    float o[8][4];
#pragma unroll
    for (int d = 0; d < 8; ++d)
#pragma unroll
        for (int k = 0; k < 4; ++k) o[d][k] = 0.f;

    const int sub = lane >> 3, r = lane & 7;

    CP_WAIT(1);
    __syncthreads();

    // Q fragments: loaded once, reused for all kv tiles
    uint32_t qf[4][4];
    {
        const int qRow = wid * 16 + ((sub & 1) ? 8 : 0) + r;
        const int qCol = (sub & 2) ? 8 : 0;
        uint32_t base = qs0 + (uint32_t)(qRow * FS + qCol) * 2;
#pragma unroll
        for (int ks = 0; ks < 4; ++ks) ldsm_x4(qf[ks], base + (uint32_t)(ks * 16) * 2);
    }

    // lane bases for K (b-frag, non-trans) and V (b-frag, trans)
    const int kRow = ((sub & 2) ? 8 : 0) + r, kCol = (sub & 1) ? 8 : 0;
    const int vRow = ((sub & 1) ? 8 : 0) + r, vCol = (sub & 2) ? 8 : 0;

    for (int kt = 0; kt < FNT; ++kt) {
        const int st = kt & 1;
        if (kt > 0) {
            if (kt < FNT - 1) CP_WAIT(1); else CP_WAIT(0);
            __syncthreads();
        }

        // ---- S = Q K^T ----
        float s[8][4];
#pragma unroll
        for (int n = 0; n < 8; ++n)
#pragma unroll
            for (int k = 0; k < 4; ++k) s[n][k] = 0.f;

        const uint32_t kBase = ks0 + (uint32_t)(st * FBK * FS + kRow * FS + kCol) * 2;
#pragma unroll
        for (int ks = 0; ks < 4; ++ks) {
#pragma unroll
            for (int np = 0; np < 4; ++np) {
                uint32_t bf[4];
                ldsm_x4(bf, kBase + (uint32_t)(np * 16 * FS + ks * 16) * 2);
                mma16816(s[2 * np + 0], qf[ks], bf[0], bf[1]);
                mma16816(s[2 * np + 1], qf[ks], bf[2], bf[3]);
            }
        }

        // ---- online softmax (exp2 domain) ----
        float tA = -CUDART_INF_F, tB = -CUDART_INF_F;
#pragma unroll
        for (int n = 0; n < 8; ++n) {
            s[n][0] *= qsA; s[n][1] *= qsA;
            s[n][2] *= qsB; s[n][3] *= qsB;
            tA = fmaxf(tA, fmaxf(s[n][0], s[n][1]));
            tB = fmaxf(tB, fmaxf(s[n][2], s[n][3]));
        }
        tA = fmaxf(tA, __shfl_xor_sync(0xffffffffu, tA, 1));
        tA = fmaxf(tA, __shfl_xor_sync(0xffffffffu, tA, 2));
        tB = fmaxf(tB, __shfl_xor_sync(0xffffffffu, tB, 1));
        tB = fmaxf(tB, __shfl_xor_sync(0xffffffffu, tB, 2));

        float mAn = fmaxf(mA, tA), mBn = fmaxf(mB, tB);
        float cA = exp2f(mA - mAn), cB = exp2f(mB - mBn);
        mA = mAn; mB = mBn;

        float sumA = 0.f, sumB = 0.f;
#pragma unroll
        for (int n = 0; n < 8; ++n) {
            s[n][0] = exp2f(s[n][0] - mA); s[n][1] = exp2f(s[n][1] - mA);
            s[n][2] = exp2f(s[n][2] - mB); s[n][3] = exp2f(s[n][3] - mB);
            sumA += s[n][0] + s[n][1];
            sumB += s[n][2] + s[n][3];
        }
        sumA += __shfl_xor_sync(0xffffffffu, sumA, 1);
        sumA += __shfl_xor_sync(0xffffffffu, sumA, 2);
        sumB += __shfl_xor_sync(0xffffffffu, sumB, 1);
        sumB += __shfl_xor_sync(0xffffffffu, sumB, 2);
        lA = lA * cA + sumA;
        lB = lB * cB + sumB;

#pragma unroll
        for (int d = 0; d < 8; ++d) {
            o[d][0] *= cA; o[d][1] *= cA;
            o[d][2] *= cB; o[d][3] *= cB;
        }

        // ---- O += P V : P c-frags map directly onto a-frags ----
        const uint32_t vBase = vs0 + (uint32_t)(st * FBK * FS + vRow * FS + vCol) * 2;
#pragma unroll
        for (int ks = 0; ks < 4; ++ks) {
            uint32_t pa[4];
            pa[0] = pack_h2(s[2 * ks][0], s[2 * ks][1]);
            pa[1] = pack_h2(s[2 * ks][2], s[2 * ks][3]);
            pa[2] = pack_h2(s[2 * ks + 1][0], s[2 * ks + 1][1]);
            pa[3] = pack_h2(s[2 * ks + 1][2], s[2 * ks + 1][3]);
#pragma unroll
            for (int dp = 0; dp < 4; ++dp) {
                uint32_t bf[4];
                ldsm_x4_t(bf, vBase + (uint32_t)(ks * 16 * FS + dp * 16) * 2);
                mma16816(o[2 * dp + 0], pa, bf[0], bf[1]);
                mma16816(o[2 * dp + 1], pa, bf[2], bf[3]);
            }
        }
        __syncthreads();
        if (kt + 2 < FNT) load_kv(kt + 2, st);
    }

    // ---- epilogue ----
    const float iA = 1.0f / lA, iB = 1.0f / lB;
#pragma unroll
    for (int d = 0; d < 8; ++d) {
        int col = h * HEAD_DIM + d * 8 + 2 * tig;
        __half2* p0 = (__half2*)(O + (size_t)(b * SEQ + rowA) * D_MODEL + col);
        __half2* p1 = (__half2*)(O + (size_t)(b * SEQ + rowA + 8) * D_MODEL + col);
        *p0 = __floats2half2_rn(o[d][0] * iA, o[d][1] * iA);
        *p1 = __floats2half2_rn(o[d][2] * iB, o[d][3] * iB);
    }
}

// ---------------- launch ------------------------------------------------------
extern "C" void kernel_launch(void* const* d_in, const int* in_sizes, int n_in,
                              void* d_out, int out_size) {
    const float* query = (const float*)d_in[0];
    const float* key   = (const float*)d_in[1];
    const float* value = (const float*)d_in[2];
    const float* phi   = (const float*)d_in[3];
    const float* Wq = (const float*)d_in[5];
    const float* bq = (const float*)d_in[6];
    const float* Wk = (const float*)d_in[7];
    const float* bk = (const float*)d_in[8];
    const float* Wv = (const float*)d_in[9];
    const float* bv = (const float*)d_in[10];
    const float* Wo = (const float*)d_in[11];
    const float* bo = (const float*)d_in[12];
    float* out = (float*)d_out;

    __half *hA, *hW, *hq, *hk, *hv, *hattn;
    float *scale_p;
    cudaGetSymbolAddress((void**)&hA, g_hA);
    cudaGetSymbolAddress((void**)&hW, g_hW);
    cudaGetSymbolAddress((void**)&hq, g_hq);
    cudaGetSymbolAddress((void**)&hk, g_hk);
    cudaGetSymbolAddress((void**)&hv, g_hv);
    cudaGetSymbolAddress((void**)&hattn, g_hattn);
    cudaGetSymbolAddress((void**)&scale_p, g_scale);

    scale_kernel<<<(MTOT + 255) / 256, 256>>>(phi, scale_p);

    const int nA8 = MTOT * D_MODEL / 8;
    const int nW8 = D_MODEL * D_MODEL / 8;
    dim3 ggrid(D_MODEL / 128, MTOT / 128);

    // Q
    f2h_kernel<<<(nA8 + 255) / 256, 256>>>((const float4*)query, (uint4*)hA, nA8);
    f2h_kernel<<<(nW8 + 255) / 256, 256>>>((const float4*)Wq, (uint4*)hW, nW8);
    gemm_h<__half><<<ggrid, 256>>>(hA, hW, bq, hq);
    // K
    f2h_kernel<<<(nA8 + 255) / 256, 256>>>((const float4*)key, (uint4*)hA, nA8);
    f2h_kernel<<<(nW8 + 255) / 256, 256>>>((const float4*)Wk, (uint4*)hW, nW8);
    gemm_h<__half><<<ggrid, 256>>>(hA, hW, bk, hk);
    // V
    f2h_kernel<<<(nA8 + 255) / 256, 256>>>((const float4*)value, (uint4*)hA, nA8);
    f2h_kernel<<<(nW8 + 255) / 256, 256>>>((const float4*)Wv, (uint4*)hW, nW8);
    gemm_h<__half><<<ggrid, 256>>>(hA, hW, bv, hv);

    // attention (fp16 in/out, fp32 softmax state)
    const int fsmem = (FBQ * FS + 4 * FBK * FS) * sizeof(__half);
    cudaFuncSetAttribute(flash_h, cudaFuncAttributeMaxDynamicSharedMemorySize, fsmem);
    dim3 fgrid(SEQ / FBQ, NUM_HEADS, BATCH);
    flash_h<<<fgrid, 256, fsmem>>>(hq, hk, hv, scale_p, hattn);

    // output projection (fp32 out)
    f2h_kernel<<<(nW8 + 255) / 256, 256>>>((const float4*)Wo, (uint4*)hW, nW8);
    gemm_h<float><<<ggrid, 256>>>(hattn, hW, bo, out);
}